// round 1
// baseline (speedup 1.0000x reference)
#include <cuda_runtime.h>
#include <cuda_bf16.h>

// Fused Conv3d(8->8, k=3, same zero-pad) + sigmoid(gelu_tanh(relu(y))) + bias
// B=8, D=32, H=128, W=128. fp32, packed f32x2 FMAs (Blackwell fma.rn.f32x2).
//
// Decomposition: grid = B * D * (H/16) = 2048 blocks, 256 threads.
// Block handles one (b, d, 16-row H tile), all 8 output channels, full W=128.
// Thread (tid): hh = tid>>4 (row in tile), wg = tid&15, w0 = wg*8 (8 W pixels).
// Accumulators: 8 cout x 4 f32x2 pixel-pairs = 32 u64 registers.
// Input staged per-cin in SMEM: 3 depth slices x 18 rows x 128 cols (row pad
// to 132 floats to skew banks). W halo via __shfl from neighbor lanes.
// Weights pre-splatted (w,w) in SMEM for direct f32x2 broadcast operands.

#define CIN   8
#define COUT  8
#define DD    32
#define HH_   128
#define WW    128
#define HWSZ  16384       // H*W
#define TH    16          // H rows per block
#define ROWP  132         // padded smem row stride (floats), 528B = 33*16B

typedef unsigned long long u64;

__device__ __forceinline__ u64 pk2(float lo, float hi) {
    u64 r;
    asm("mov.b64 %0, {%1, %2};" : "=l"(r) : "f"(lo), "f"(hi));
    return r;
}
__device__ __forceinline__ void fma2(u64& d, u64 a, u64 b) {
    asm("fma.rn.f32x2 %0, %1, %2, %0;" : "+l"(d) : "l"(a), "l"(b));
}
__device__ __forceinline__ float2 up2(u64 v) {
    float lo, hi;
    asm("mov.b64 {%0, %1}, %2;" : "=f"(lo), "=f"(hi) : "l"(v));
    return make_float2(lo, hi);
}

// sigmoid(gelu_tanh(relu(y))): for yr=relu(y)>=0,
//   gelu = 0.5*yr*(1+tanh(t)) = yr * sigmoid(2t),  t = 0.79788456*(yr + 0.044715*yr^3)
__device__ __forceinline__ float act_chain(float y) {
    float yr = fmaxf(y, 0.0f);
    float q  = fmaf(0.044715f * yr, yr, 1.0f);
    float t2 = 1.5957691216057308f * yr * q;          // 2*t
    float g  = yr * __fdividef(1.0f, 1.0f + __expf(-t2));
    return __fdividef(1.0f, 1.0f + __expf(-g));
}

__global__ void __launch_bounds__(256, 2)
conv3d_fused_kernel(const float* __restrict__ x,
                    const float* __restrict__ wgt,
                    const float* __restrict__ bias,
                    float* __restrict__ out)
{
    __shared__ __align__(16) float sIn[3 * 18 * ROWP];   // 7128 f = 28512 B
    __shared__ u64 sW[CIN * 3 * 3 * 3 * COUT];           // 1728 u64 = 13824 B

    const int tid  = threadIdx.x;
    const int bx   = blockIdx.x;
    const int ht   = bx & 7;          // H tile index (0..7)
    const int dpos = (bx >> 3) & 31;  // depth
    const int b    = bx >> 8;         // batch
    const int h0   = ht << 4;

    // --- pre-splat weights into shared: [(ci*3+kd)*3+kh][kw*8+co] as (w,w) ---
    for (int i = tid; i < 1728; i += 256) {
        int co  = i / 216;  int rem = i - co * 216;
        int ci  = rem / 27; int r2  = rem - ci * 27;
        int kd  = r2 / 9;   int r3  = r2 - kd * 9;
        int kh  = r3 / 3;   int kw  = r3 - kh * 3;
        float w = wgt[i];   // global layout [co][ci][kd][kh][kw] linear == i
        sW[((ci * 3 + kd) * 3 + kh) * 24 + kw * 8 + co] = pk2(w, w);
    }

    const int hh = tid >> 4;     // 0..15  (row within tile)
    const int wg = tid & 15;     // 0..15  (8-pixel W group)
    const int w0 = wg << 3;

    u64 acc[32];
    #pragma unroll
    for (int k = 0; k < 32; ++k) acc[k] = 0ull;

    for (int ci = 0; ci < CIN; ++ci) {
        __syncthreads();   // protect previous slab (and weights on iter 0)

        // --- stage 3 x 18 x 128 input slab for this cin (zero-pad D/H) ---
        const float* xb = x + ((size_t)((b * CIN + ci) * DD) << 14);
        for (int i = tid; i < 3 * 18 * 128; i += 256) {      // 6912 = 27*256
            int dz = i / 2304;  int r = i - dz * 2304;
            int hz = r >> 7;    int w = r & 127;
            int dd = dpos + dz - 1;
            int hg = h0 + hz - 1;
            float v = 0.0f;
            if ((unsigned)dd < 32u && (unsigned)hg < 128u)
                v = xb[(dd << 14) + (hg << 7) + w];
            sIn[(dz * 18 + hz) * ROWP + w] = v;
        }
        __syncthreads();

        #pragma unroll 1
        for (int kd = 0; kd < 3; ++kd) {
            #pragma unroll
            for (int kh = 0; kh < 3; ++kh) {
                const float4* rp = reinterpret_cast<const float4*>(
                    &sIn[(kd * 18 + hh + kh) * ROWP + w0]);
                float4 v0 = rp[0];
                float4 v1 = rp[1];
                // W halo from neighbor lanes (lanes 0..15 row A, 16..31 row B)
                float xm1 = __shfl_up_sync(0xffffffffu, v1.w, 1);
                float xp8 = __shfl_down_sync(0xffffffffu, v0.x, 1);
                if (wg == 0)  xm1 = 0.0f;   // w = -1  zero pad
                if (wg == 15) xp8 = 0.0f;   // w = 128 zero pad

                u64 A  = pk2(xm1, v0.x);
                u64 N0 = pk2(v0.x, v0.y), N1 = pk2(v0.z, v0.w);
                u64 N2 = pk2(v1.x, v1.y), N3 = pk2(v1.z, v1.w);
                u64 S0 = pk2(v0.y, v0.z), S1 = pk2(v0.w, v1.x), S2 = pk2(v1.y, v1.z);
                u64 E  = pk2(v1.w, xp8);

                const u64* wp = &sW[((ci * 3 + kd) * 3 + kh) * 24];
                #pragma unroll
                for (int co = 0; co < COUT; ++co) {
                    u64 wa = wp[co];          // kw = 0 (dw = -1)
                    fma2(acc[co * 4 + 0], A,  wa);
                    fma2(acc[co * 4 + 1], S0, wa);
                    fma2(acc[co * 4 + 2], S1, wa);
                    fma2(acc[co * 4 + 3], S2, wa);
                    u64 wb = wp[8 + co];      // kw = 1 (dw = 0)
                    fma2(acc[co * 4 + 0], N0, wb);
                    fma2(acc[co * 4 + 1], N1, wb);
                    fma2(acc[co * 4 + 2], N2, wb);
                    fma2(acc[co * 4 + 3], N3, wb);
                    u64 wc = wp[16 + co];     // kw = 2 (dw = +1)
                    fma2(acc[co * 4 + 0], S0, wc);
                    fma2(acc[co * 4 + 1], S1, wc);
                    fma2(acc[co * 4 + 2], S2, wc);
                    fma2(acc[co * 4 + 3], E,  wc);
                }
            }
        }
    }

    // --- epilogue: activation chain + bias, vectorized stores ---
    const int hout = h0 + hh;
    #pragma unroll
    for (int co = 0; co < COUT; ++co) {
        float bb = bias[co];
        float o[8];
        #pragma unroll
        for (int j = 0; j < 4; ++j) {
            float2 p = up2(acc[co * 4 + j]);
            o[2 * j]     = p.x;
            o[2 * j + 1] = p.y;
        }
        #pragma unroll
        for (int k = 0; k < 8; ++k)
            o[k] = act_chain(o[k]) + bb;

        float4* dst = reinterpret_cast<float4*>(
            out + ((size_t)((b * COUT + co) * DD + dpos) << 14) + (hout << 7) + w0);
        dst[0] = make_float4(o[0], o[1], o[2], o[3]);
        dst[1] = make_float4(o[4], o[5], o[6], o[7]);
    }
}

extern "C" void kernel_launch(void* const* d_in, const int* in_sizes, int n_in,
                              void* d_out, int out_size)
{
    const float* x    = (const float*)d_in[0];   // (8,8,32,128,128)
    const float* wgt  = (const float*)d_in[1];   // (8,8,3,3,3)
    const float* bias = (const float*)d_in[2];   // (8,1,1,1)
    float* out = (float*)d_out;                  // (8,8,32,128,128)

    // grid = 8 H-tiles * 32 depths * 8 batches = 2048 blocks
    conv3d_fused_kernel<<<2048, 256>>>(x, wgt, bias, out);
}

// round 2
// speedup vs baseline: 1.3012x; 1.3012x over previous
#include <cuda_runtime.h>
#include <cuda_bf16.h>

// Fused Conv3d(8->8, k=3, same zero-pad) + sigmoid(gelu_tanh(relu(y))) + bias
// B=8, D=32, H=128, W=128. fp32, packed f32x2 FMAs.
//
// Round-2 redesign: ALL fma.rn.f32x2 operands come from SMEM as naturally
// aligned register pairs (LDS.64/LDS.128) -- no mov.b64 packing, no shuffles,
// no edge predicates in the hot loop. Achieved by staging a second W-shifted
// copy of each row: sS[k] = x[k-1] (k=0 / k=129 are the zero pads).
//
// grid = B*D*(H/16) = 2048 blocks, 256 threads.
// Thread: hh = tid>>4 (row 0..15), wg = tid&15, w0 = wg*8 (8 W pixels).
// Accumulators: 8 cout x 4 f32x2 pairs = 32 u64.
// Staging: one (ci, depth-slice) at a time -> SMEM fits statically.

#define ROWP 132   // padded row stride in floats (528B, 16B-multiple)

typedef unsigned long long u64;

__device__ __forceinline__ void fma2(u64& d, u64 a, u64 b) {
    asm("fma.rn.f32x2 %0, %1, %2, %0;" : "+l"(d) : "l"(a), "l"(b));
}
__device__ __forceinline__ u64 pk2(float lo, float hi) {
    u64 r;
    asm("mov.b64 %0, {%1, %2};" : "=l"(r) : "f"(lo), "f"(hi));
    return r;
}
__device__ __forceinline__ float2 up2(u64 v) {
    float lo, hi;
    asm("mov.b64 {%0, %1}, %2;" : "=f"(lo), "=f"(hi) : "l"(v));
    return make_float2(lo, hi);
}

// sigmoid(gelu_tanh(relu(y))): for yr=relu(y)>=0,
//   gelu = 0.5*yr*(1+tanh(t)) = yr * sigmoid(2t),  t = 0.79788456*(yr + 0.044715*yr^3)
__device__ __forceinline__ float act_chain(float y) {
    float yr = fmaxf(y, 0.0f);
    float q  = fmaf(0.044715f * yr, yr, 1.0f);
    float t2 = 1.5957691216057308f * yr * q;          // 2*t
    float g  = yr * __fdividef(1.0f, 1.0f + __expf(-t2));
    return __fdividef(1.0f, 1.0f + __expf(-g));
}

__global__ void __launch_bounds__(256, 2)
conv3d_fused_kernel(const float* __restrict__ x,
                    const float* __restrict__ wgt,
                    const float* __restrict__ bias,
                    float* __restrict__ out)
{
    // One depth slice staged at a time: 18 rows (h0-1 .. h0+16).
    __shared__ __align__(16) float sC[18 * ROWP];   // sC[r][w]   = x[r][w]
    __shared__ __align__(16) float sS[18 * ROWP];   // sS[r][k]   = x[r][k-1]
    __shared__ u64 sW[8 * 27 * 8];                  // 1728 (w,w) pairs = 13.5KB

    const int tid  = threadIdx.x;
    const int bx   = blockIdx.x;
    const int ht   = bx & 7;
    const int dpos = (bx >> 3) & 31;
    const int b    = bx >> 8;
    const int h0   = ht << 4;

    // weights pre-splatted: [(ci*3+kd)*3+kh][kw*8+co] as (w,w)
    for (int i = tid; i < 1728; i += 256) {
        int co  = i / 216;  int rem = i - co * 216;
        int ci  = rem / 27; int r2  = rem - ci * 27;
        int kd  = r2 / 9;   int r3  = r2 - kd * 9;
        int kh  = r3 / 3;   int kw  = r3 - kh * 3;
        float w = wgt[i];
        sW[((ci * 3 + kd) * 3 + kh) * 24 + kw * 8 + co] = pk2(w, w);
    }
    // W zero-pads of the shifted copy: sS[r][0] = x[-1] = 0, sS[r][129] = x[128] = 0.
    // Staging only ever writes k = 1..128, so init once.
    if (tid < 18) {
        sS[tid * ROWP + 0]   = 0.0f;
        sS[tid * ROWP + 129] = 0.0f;
    }

    const int hh = tid >> 4;     // row in tile
    const int wg = tid & 15;
    const int w0 = wg << 3;

    u64 acc[32];
    #pragma unroll
    for (int k = 0; k < 32; ++k) acc[k] = 0ull;

    for (int ci = 0; ci < 8; ++ci) {
        const float* xb = x + ((size_t)((b * 8 + ci) * 32) << 14);
        #pragma unroll 1
        for (int dz = 0; dz < 3; ++dz) {
            const int dd = dpos + dz - 1;
            if ((unsigned)dd >= 32u) continue;   // zero slice: contributes nothing (uniform)

            __syncthreads();  // protect previous slab (and sW/sS pads on iter 0)

            // stage slice (ci, dd): 18 rows x 128 cols, both copies
            const float* xs = xb + ((size_t)dd << 14);
            for (int i = tid; i < 18 * 128; i += 256) {     // 9 per thread
                int hz = i >> 7, w = i & 127;
                int hg = h0 + hz - 1;
                float v = 0.0f;
                if ((unsigned)hg < 128u) v = xs[(hg << 7) + w];
                sC[hz * ROWP + w]     = v;
                sS[hz * ROWP + w + 1] = v;
            }
            __syncthreads();

            #pragma unroll
            for (int kh = 0; kh < 3; ++kh) {
                const int roff = (hh + kh) * ROWP;
                // center pairs: (x[w0+2j], x[w0+2j+1]), j=0..3
                const ulonglong2* cp = reinterpret_cast<const ulonglong2*>(&sC[roff + w0]);
                ulonglong2 ca = cp[0];    // P_ctr0, P_ctr1
                ulonglong2 cb = cp[1];    // P_ctr2, P_ctr3
                // left pairs: (x[w0+2j-1], x[w0+2j]) = sS pair at k = w0+2j
                const ulonglong2* sp = reinterpret_cast<const ulonglong2*>(&sS[roff + w0]);
                ulonglong2 sa = sp[0];    // P_left0, P_left1
                ulonglong2 sb = sp[1];    // P_left2, P_left3
                // right pairs j=0..2 == left pairs j=1..3; last one:
                u64 sr3 = *reinterpret_cast<const u64*>(&sS[roff + w0 + 8]); // P_right3

                const u64* wp = &sW[((ci * 3 + dz) * 3 + kh) * 24];
                #pragma unroll
                for (int co = 0; co < 8; ++co) {
                    u64 wL = wp[co];        // kw=0 (dw=-1) -> left pairs
                    fma2(acc[co * 4 + 0], sa.x, wL);
                    fma2(acc[co * 4 + 1], sa.y, wL);
                    fma2(acc[co * 4 + 2], sb.x, wL);
                    fma2(acc[co * 4 + 3], sb.y, wL);
                    u64 wC = wp[8 + co];    // kw=1 (dw=0) -> center pairs
                    fma2(acc[co * 4 + 0], ca.x, wC);
                    fma2(acc[co * 4 + 1], ca.y, wC);
                    fma2(acc[co * 4 + 2], cb.x, wC);
                    fma2(acc[co * 4 + 3], cb.y, wC);
                    u64 wR = wp[16 + co];   // kw=2 (dw=+1) -> right pairs
                    fma2(acc[co * 4 + 0], sa.y, wR);
                    fma2(acc[co * 4 + 1], sb.x, wR);
                    fma2(acc[co * 4 + 2], sb.y, wR);
                    fma2(acc[co * 4 + 3], sr3, wR);
                }
            }
        }
    }

    // --- epilogue: activation chain + bias, vectorized stores ---
    const int hout = h0 + hh;
    #pragma unroll
    for (int co = 0; co < 8; ++co) {
        float bb = bias[co];
        float o[8];
        #pragma unroll
        for (int j = 0; j < 4; ++j) {
            float2 p = up2(acc[co * 4 + j]);
            o[2 * j]     = p.x;
            o[2 * j + 1] = p.y;
        }
        #pragma unroll
        for (int k = 0; k < 8; ++k)
            o[k] = act_chain(o[k]) + bb;

        float4* dst = reinterpret_cast<float4*>(
            out + ((size_t)((b * 8 + co) * 32 + dpos) << 14) + (hout << 7) + w0);
        dst[0] = make_float4(o[0], o[1], o[2], o[3]);
        dst[1] = make_float4(o[4], o[5], o[6], o[7]);
    }
}

extern "C" void kernel_launch(void* const* d_in, const int* in_sizes, int n_in,
                              void* d_out, int out_size)
{
    const float* x    = (const float*)d_in[0];   // (8,8,32,128,128)
    const float* wgt  = (const float*)d_in[1];   // (8,8,3,3,3)
    const float* bias = (const float*)d_in[2];   // (8,1,1,1)
    float* out = (float*)d_out;                  // (8,8,32,128,128)

    conv3d_fused_kernel<<<2048, 256>>>(x, wgt, bias, out);
}

// round 3
// speedup vs baseline: 1.3450x; 1.0337x over previous
#include <cuda_runtime.h>
#include <cuda_bf16.h>

// Fused Conv3d(8->8, k=3, same zero-pad) + sigmoid(gelu_tanh(relu(y))) + bias
// B=8, D=32, H=128, W=128. fp32, packed f32x2 FMAs.
//
// Round-3: halve LSU instruction count in the hot loop.
//  - weight loads: ulonglong2 (2 couts per LDS.128) -> 12 loads/kh instead of 24
//  - staging: float4 LDG/STS
// All fma.rn.f32x2 operands remain naturally aligned SMEM pairs (sS is a
// 1-element W-shifted copy with baked-in zero pads).

#define ROWP 132   // padded row stride in floats (528B = 33*16B)

typedef unsigned long long u64;

__device__ __forceinline__ void fma2(u64& d, u64 a, u64 b) {
    asm("fma.rn.f32x2 %0, %1, %2, %0;" : "+l"(d) : "l"(a), "l"(b));
}
__device__ __forceinline__ u64 pk2(float lo, float hi) {
    u64 r;
    asm("mov.b64 %0, {%1, %2};" : "=l"(r) : "f"(lo), "f"(hi));
    return r;
}
__device__ __forceinline__ float2 up2(u64 v) {
    float lo, hi;
    asm("mov.b64 {%0, %1}, %2;" : "=f"(lo), "=f"(hi) : "l"(v));
    return make_float2(lo, hi);
}

// sigmoid(gelu_tanh(relu(y))): for yr=relu(y)>=0,
//   gelu = 0.5*yr*(1+tanh(t)) = yr * sigmoid(2t),  t = 0.79788456*(yr + 0.044715*yr^3)
__device__ __forceinline__ float act_chain(float y) {
    float yr = fmaxf(y, 0.0f);
    float q  = fmaf(0.044715f * yr, yr, 1.0f);
    float t2 = 1.5957691216057308f * yr * q;          // 2*t
    float g  = yr * __fdividef(1.0f, 1.0f + __expf(-t2));
    return __fdividef(1.0f, 1.0f + __expf(-g));
}

__global__ void __launch_bounds__(256, 2)
conv3d_fused_kernel(const float* __restrict__ x,
                    const float* __restrict__ wgt,
                    const float* __restrict__ bias,
                    float* __restrict__ out)
{
    __shared__ __align__(16) float sC[18 * ROWP];   // sC[r][w] = x[r][w]
    __shared__ __align__(16) float sS[18 * ROWP];   // sS[r][k] = x[r][k-1]
    __shared__ __align__(16) u64 sW[8 * 27 * 8];    // (w,w) pairs, co contiguous

    const int tid  = threadIdx.x;
    const int bx   = blockIdx.x;
    const int ht   = bx & 7;
    const int dpos = (bx >> 3) & 31;
    const int b    = bx >> 8;
    const int h0   = ht << 4;

    // weights pre-splatted: [(ci*3+kd)*3+kh][kw*8+co] as (w,w)
    for (int i = tid; i < 1728; i += 256) {
        int co  = i / 216;  int rem = i - co * 216;
        int ci  = rem / 27; int r2  = rem - ci * 27;
        int kd  = r2 / 9;   int r3  = r2 - kd * 9;
        int kh  = r3 / 3;   int kw  = r3 - kh * 3;
        float w = wgt[i];
        sW[((ci * 3 + kd) * 3 + kh) * 24 + kw * 8 + co] = pk2(w, w);
    }
    // W zero-pads of the shifted copy (staging only writes k = 1..128)
    if (tid < 18) {
        sS[tid * ROWP + 0]   = 0.0f;
        sS[tid * ROWP + 129] = 0.0f;
    }

    const int hh = tid >> 4;     // row in tile (0..15)
    const int wg = tid & 15;
    const int w0 = wg << 3;

    u64 acc[32];
    #pragma unroll
    for (int k = 0; k < 32; ++k) acc[k] = 0ull;

    for (int ci = 0; ci < 8; ++ci) {
        const float* xb = x + ((size_t)((b * 8 + ci) * 32) << 14);
        #pragma unroll 1
        for (int dz = 0; dz < 3; ++dz) {
            const int dd = dpos + dz - 1;
            if ((unsigned)dd >= 32u) continue;   // zero slice contributes nothing

            __syncthreads();  // protect previous slab (and sW/pads on iter 0)

            // stage slice (ci, dd): 18 rows x 128 cols, both copies, float4
            const float4* xs4 = reinterpret_cast<const float4*>(xb + ((size_t)dd << 14));
            for (int i = tid; i < 18 * 32; i += 256) {     // 2.25 iters
                int hz = i >> 5, w4 = i & 31;
                int hg = h0 + hz - 1;
                float4 v = make_float4(0.f, 0.f, 0.f, 0.f);
                if ((unsigned)hg < 128u) v = xs4[(hg << 5) + w4];
                *reinterpret_cast<float4*>(&sC[hz * ROWP + (w4 << 2)]) = v;
                float* s = &sS[hz * ROWP + (w4 << 2) + 1];
                s[0] = v.x;
                *reinterpret_cast<float2*>(s + 1) = make_float2(v.y, v.z);
                s[3] = v.w;
            }
            __syncthreads();

            #pragma unroll
            for (int kh = 0; kh < 3; ++kh) {
                const int roff = (hh + kh) * ROWP;
                const ulonglong2* cp = reinterpret_cast<const ulonglong2*>(&sC[roff + w0]);
                ulonglong2 ca = cp[0];    // center pairs 0,1
                ulonglong2 cb = cp[1];    // center pairs 2,3
                const ulonglong2* sp = reinterpret_cast<const ulonglong2*>(&sS[roff + w0]);
                ulonglong2 sa = sp[0];    // left pairs 0,1
                ulonglong2 sb = sp[1];    // left pairs 2,3
                u64 sr3 = *reinterpret_cast<const u64*>(&sS[roff + w0 + 8]); // right pair 3

                const u64* wp = &sW[((ci * 3 + dz) * 3 + kh) * 24];
                #pragma unroll
                for (int cp2 = 0; cp2 < 4; ++cp2) {   // co pairs (2 couts each)
                    ulonglong2 wL = *reinterpret_cast<const ulonglong2*>(wp + 2 * cp2);
                    ulonglong2 wC = *reinterpret_cast<const ulonglong2*>(wp + 8 + 2 * cp2);
                    ulonglong2 wR = *reinterpret_cast<const ulonglong2*>(wp + 16 + 2 * cp2);
                    u64* a0 = &acc[(2 * cp2) * 4];
                    u64* a1 = &acc[(2 * cp2 + 1) * 4];
                    // cout 2*cp2
                    fma2(a0[0], sa.x, wL.x);  fma2(a0[1], sa.y, wL.x);
                    fma2(a0[2], sb.x, wL.x);  fma2(a0[3], sb.y, wL.x);
                    fma2(a0[0], ca.x, wC.x);  fma2(a0[1], ca.y, wC.x);
                    fma2(a0[2], cb.x, wC.x);  fma2(a0[3], cb.y, wC.x);
                    fma2(a0[0], sa.y, wR.x);  fma2(a0[1], sb.x, wR.x);
                    fma2(a0[2], sb.y, wR.x);  fma2(a0[3], sr3, wR.x);
                    // cout 2*cp2+1
                    fma2(a1[0], sa.x, wL.y);  fma2(a1[1], sa.y, wL.y);
                    fma2(a1[2], sb.x, wL.y);  fma2(a1[3], sb.y, wL.y);
                    fma2(a1[0], ca.x, wC.y);  fma2(a1[1], ca.y, wC.y);
                    fma2(a1[2], cb.x, wC.y);  fma2(a1[3], cb.y, wC.y);
                    fma2(a1[0], sa.y, wR.y);  fma2(a1[1], sb.x, wR.y);
                    fma2(a1[2], sb.y, wR.y);  fma2(a1[3], sr3, wR.y);
                }
            }
        }
    }

    // --- epilogue: activation chain + bias, vectorized coalesced stores ---
    const int hout = h0 + hh;
    #pragma unroll
    for (int co = 0; co < 8; ++co) {
        float bb = bias[co];
        float o[8];
        #pragma unroll
        for (int j = 0; j < 4; ++j) {
            float2 p = up2(acc[co * 4 + j]);
            o[2 * j]     = p.x;
            o[2 * j + 1] = p.y;
        }
        #pragma unroll
        for (int k = 0; k < 8; ++k)
            o[k] = act_chain(o[k]) + bb;

        float4* dst = reinterpret_cast<float4*>(
            out + ((size_t)((b * 8 + co) * 32 + dpos) << 14) + (hout << 7) + w0);
        dst[0] = make_float4(o[0], o[1], o[2], o[3]);
        dst[1] = make_float4(o[4], o[5], o[6], o[7]);
    }
}

extern "C" void kernel_launch(void* const* d_in, const int* in_sizes, int n_in,
                              void* d_out, int out_size)
{
    const float* x    = (const float*)d_in[0];   // (8,8,32,128,128)
    const float* wgt  = (const float*)d_in[1];   // (8,8,3,3,3)
    const float* bias = (const float*)d_in[2];   // (8,1,1,1)
    float* out = (float*)d_out;                  // (8,8,32,128,128)

    conv3d_fused_kernel<<<2048, 256>>>(x, wgt, bias, out);
}

// round 4
// speedup vs baseline: 1.5368x; 1.1426x over previous
#include <cuda_runtime.h>
#include <cuda_bf16.h>

// Fused Conv3d(8->8, k=3, same zero-pad) + sigmoid(gelu_tanh(relu(y))) + bias
// B=8, D=32, H=128, W=128. fp32, packed f32x2 FMAs.
//
// Round-4:
//  - weights moved to __constant__ (dedicated const port, off the L1 crossbar):
//    prep kernel splats (w,w) pairs -> __device__ buffer -> MemcpyToSymbol node.
//  - sS (W-shifted copy) staged via conflict-free stride-1 copy pass instead of
//    4-way-bank-conflicted split stores.
// All fma.rn.f32x2 operands are naturally aligned SMEM pairs or const loads.

#define ROWP 132   // padded row stride in floats (528B = 33*16B)

typedef unsigned long long u64;

__constant__ __align__(16) u64 cW[1728];     // splatted (w,w), [(ci*3+kd)*3+kh][kw*8+co]
__device__   __align__(16) u64 gW_buf[1728]; // staging buffer for the memcpy node

__device__ __forceinline__ void fma2(u64& d, u64 a, u64 b) {
    asm("fma.rn.f32x2 %0, %1, %2, %0;" : "+l"(d) : "l"(a), "l"(b));
}
__device__ __forceinline__ u64 pk2(float lo, float hi) {
    u64 r;
    asm("mov.b64 %0, {%1, %2};" : "=l"(r) : "f"(lo), "f"(hi));
    return r;
}
__device__ __forceinline__ float2 up2(u64 v) {
    float lo, hi;
    asm("mov.b64 {%0, %1}, %2;" : "=f"(lo), "=f"(hi) : "l"(v));
    return make_float2(lo, hi);
}

// sigmoid(gelu_tanh(relu(y))): for yr=relu(y)>=0,
//   gelu = 0.5*yr*(1+tanh(t)) = yr * sigmoid(2t),  t = 0.79788456*(yr + 0.044715*yr^3)
__device__ __forceinline__ float act_chain(float y) {
    float yr = fmaxf(y, 0.0f);
    float q  = fmaf(0.044715f * yr, yr, 1.0f);
    float t2 = 1.5957691216057308f * yr * q;          // 2*t
    float g  = yr * __fdividef(1.0f, 1.0f + __expf(-t2));
    return __fdividef(1.0f, 1.0f + __expf(-g));
}

__global__ void weight_splat_kernel(const float* __restrict__ wgt) {
    for (int i = threadIdx.x; i < 1728; i += 256) {
        int co  = i / 216;  int rem = i - co * 216;
        int ci  = rem / 27; int r2  = rem - ci * 27;
        int kd  = r2 / 9;   int r3  = r2 - kd * 9;
        int kh  = r3 / 3;   int kw  = r3 - kh * 3;
        float w = wgt[i];   // layout [co][ci][kd][kh][kw] linear == i
        gW_buf[((ci * 3 + kd) * 3 + kh) * 24 + kw * 8 + co] = pk2(w, w);
    }
}

__global__ void __launch_bounds__(256, 2)
conv3d_fused_kernel(const float* __restrict__ x,
                    const float* __restrict__ bias,
                    float* __restrict__ out)
{
    __shared__ __align__(16) float sC[18 * ROWP];   // sC[r][w] = x[r][w]
    __shared__ __align__(16) float sS[18 * ROWP];   // sS[r][k] = x[r][k-1]

    const int tid  = threadIdx.x;
    const int bx   = blockIdx.x;
    const int ht   = bx & 7;
    const int dpos = (bx >> 3) & 31;
    const int b    = bx >> 8;
    const int h0   = ht << 4;

    // W zero-pads of the shifted copy (copy pass only writes k = 1..128)
    if (tid < 18) {
        sS[tid * ROWP + 0]   = 0.0f;
        sS[tid * ROWP + 129] = 0.0f;
    }

    const int hh = tid >> 4;     // row in tile (0..15)
    const int wg = tid & 15;
    const int w0 = wg << 3;

    u64 acc[32];
    #pragma unroll
    for (int k = 0; k < 32; ++k) acc[k] = 0ull;

    for (int ci = 0; ci < 8; ++ci) {
        const float* xb = x + ((size_t)((b * 8 + ci) * 32) << 14);
        #pragma unroll 1
        for (int dz = 0; dz < 3; ++dz) {
            const int dd = dpos + dz - 1;
            if ((unsigned)dd >= 32u) continue;   // zero slice contributes nothing

            __syncthreads();  // protect previous slab (and pads on iter 0)

            // pass 1: stage sC (ci, dd): 18 rows x 128 cols, float4
            const float4* xs4 = reinterpret_cast<const float4*>(xb + ((size_t)dd << 14));
            for (int i = tid; i < 18 * 32; i += 256) {
                int hz = i >> 5, w4 = i & 31;
                int hg = h0 + hz - 1;
                float4 v = make_float4(0.f, 0.f, 0.f, 0.f);
                if ((unsigned)hg < 128u) v = xs4[(hg << 5) + w4];
                *reinterpret_cast<float4*>(&sC[hz * ROWP + (w4 << 2)]) = v;
            }
            __syncthreads();

            // pass 2: sS[k+1] = sC[k], stride-1 (conflict-free LDS.32/STS.32)
            #pragma unroll
            for (int j = 0; j < 9; ++j) {
                int i2 = tid + j * 256;          // 0 .. 2303
                int hz = i2 >> 7, w = i2 & 127;
                sS[hz * ROWP + w + 1] = sC[hz * ROWP + w];
            }
            __syncthreads();

            #pragma unroll
            for (int kh = 0; kh < 3; ++kh) {
                const int roff = (hh + kh) * ROWP;
                const ulonglong2* cp = reinterpret_cast<const ulonglong2*>(&sC[roff + w0]);
                ulonglong2 ca = cp[0];    // center pairs 0,1
                ulonglong2 cb = cp[1];    // center pairs 2,3
                const ulonglong2* sp = reinterpret_cast<const ulonglong2*>(&sS[roff + w0]);
                ulonglong2 sa = sp[0];    // left pairs 0,1
                ulonglong2 sb = sp[1];    // left pairs 2,3
                u64 sr3 = *reinterpret_cast<const u64*>(&sS[roff + w0 + 8]); // right pair 3

                const u64* wp = &cW[((ci * 3 + dz) * 3 + kh) * 24];
                #pragma unroll
                for (int cp2 = 0; cp2 < 4; ++cp2) {   // co pairs (2 couts each)
                    ulonglong2 wL = *reinterpret_cast<const ulonglong2*>(wp + 2 * cp2);
                    ulonglong2 wC = *reinterpret_cast<const ulonglong2*>(wp + 8 + 2 * cp2);
                    ulonglong2 wR = *reinterpret_cast<const ulonglong2*>(wp + 16 + 2 * cp2);
                    u64* a0 = &acc[(2 * cp2) * 4];
                    u64* a1 = &acc[(2 * cp2 + 1) * 4];
                    fma2(a0[0], sa.x, wL.x);  fma2(a0[1], sa.y, wL.x);
                    fma2(a0[2], sb.x, wL.x);  fma2(a0[3], sb.y, wL.x);
                    fma2(a0[0], ca.x, wC.x);  fma2(a0[1], ca.y, wC.x);
                    fma2(a0[2], cb.x, wC.x);  fma2(a0[3], cb.y, wC.x);
                    fma2(a0[0], sa.y, wR.x);  fma2(a0[1], sb.x, wR.x);
                    fma2(a0[2], sb.y, wR.x);  fma2(a0[3], sr3, wR.x);
                    fma2(a1[0], sa.x, wL.y);  fma2(a1[1], sa.y, wL.y);
                    fma2(a1[2], sb.x, wL.y);  fma2(a1[3], sb.y, wL.y);
                    fma2(a1[0], ca.x, wC.y);  fma2(a1[1], ca.y, wC.y);
                    fma2(a1[2], cb.x, wC.y);  fma2(a1[3], cb.y, wC.y);
                    fma2(a1[0], sa.y, wR.y);  fma2(a1[1], sb.x, wR.y);
                    fma2(a1[2], sb.y, wR.y);  fma2(a1[3], sr3, wR.y);
                }
            }
        }
    }

    // --- epilogue: activation chain + bias, vectorized coalesced stores ---
    const int hout = h0 + hh;
    #pragma unroll
    for (int co = 0; co < 8; ++co) {
        float bb = bias[co];
        float o[8];
        #pragma unroll
        for (int j = 0; j < 4; ++j) {
            float2 p = up2(acc[co * 4 + j]);
            o[2 * j]     = p.x;
            o[2 * j + 1] = p.y;
        }
        #pragma unroll
        for (int k = 0; k < 8; ++k)
            o[k] = act_chain(o[k]) + bb;

        float4* dst = reinterpret_cast<float4*>(
            out + ((size_t)((b * 8 + co) * 32 + dpos) << 14) + (hout << 7) + w0);
        dst[0] = make_float4(o[0], o[1], o[2], o[3]);
        dst[1] = make_float4(o[4], o[5], o[6], o[7]);
    }
}

extern "C" void kernel_launch(void* const* d_in, const int* in_sizes, int n_in,
                              void* d_out, int out_size)
{
    const float* x    = (const float*)d_in[0];   // (8,8,32,128,128)
    const float* wgt  = (const float*)d_in[1];   // (8,8,3,3,3)
    const float* bias = (const float*)d_in[2];   // (8,1,1,1)
    float* out = (float*)d_out;                  // (8,8,32,128,128)

    // 1) splat weights into __device__ buffer
    weight_splat_kernel<<<1, 256>>>(wgt);
    // 2) copy into __constant__ (graph-capturable memcpy node, D2D)
    void* gw_ptr = nullptr;
    cudaGetSymbolAddress(&gw_ptr, gW_buf);
    cudaMemcpyToSymbolAsync(cW, gw_ptr, 1728 * sizeof(u64), 0,
                            cudaMemcpyDeviceToDevice, 0);
    // 3) main fused conv
    conv3d_fused_kernel<<<2048, 256>>>(x, bias, out);
}

// round 5
// speedup vs baseline: 1.9707x; 1.2823x over previous
#include <cuda_runtime.h>
#include <cuda_bf16.h>

// Fused Conv3d(8->8, k=3, same zero-pad) + sigmoid(gelu_tanh(relu(y))) + bias
// B=8, D=32, H=128, W=128. fp32, packed f32x2 FMAs.
//
// Round-5: single-pass staging. The W-shifted copy sS[k]=x[k-1] is produced
// during the load pass via lane-rotation (__shfl_up of v.w) and a second
// aligned STS.128 -- no separate copy pass, one less __syncthreads per slab.
// Weights live in __constant__ (uniform const port, off the L1 crossbar).

#define ROWP 132   // padded row stride in floats (528B = 33*16B)

typedef unsigned long long u64;

__constant__ __align__(16) u64 cW[1728];     // splatted (w,w), [(ci*3+kd)*3+kh][kw*8+co]
__device__   __align__(16) u64 gW_buf[1728]; // staging buffer for the memcpy node

__device__ __forceinline__ void fma2(u64& d, u64 a, u64 b) {
    asm("fma.rn.f32x2 %0, %1, %2, %0;" : "+l"(d) : "l"(a), "l"(b));
}
__device__ __forceinline__ u64 pk2(float lo, float hi) {
    u64 r;
    asm("mov.b64 %0, {%1, %2};" : "=l"(r) : "f"(lo), "f"(hi));
    return r;
}
__device__ __forceinline__ float2 up2(u64 v) {
    float lo, hi;
    asm("mov.b64 {%0, %1}, %2;" : "=f"(lo), "=f"(hi) : "l"(v));
    return make_float2(lo, hi);
}

// sigmoid(gelu_tanh(relu(y))): for yr=relu(y)>=0,
//   gelu = 0.5*yr*(1+tanh(t)) = yr * sigmoid(2t),  t = 0.79788456*(yr + 0.044715*yr^3)
__device__ __forceinline__ float act_chain(float y) {
    float yr = fmaxf(y, 0.0f);
    float q  = fmaf(0.044715f * yr, yr, 1.0f);
    float t2 = 1.5957691216057308f * yr * q;          // 2*t
    float g  = yr * __fdividef(1.0f, 1.0f + __expf(-t2));
    return __fdividef(1.0f, 1.0f + __expf(-g));
}

__global__ void weight_splat_kernel(const float* __restrict__ wgt) {
    for (int i = threadIdx.x; i < 1728; i += 256) {
        int co  = i / 216;  int rem = i - co * 216;
        int ci  = rem / 27; int r2  = rem - ci * 27;
        int kd  = r2 / 9;   int r3  = r2 - kd * 9;
        int kh  = r3 / 3;   int kw  = r3 - kh * 3;
        float w = wgt[i];   // layout [co][ci][kd][kh][kw] linear == i
        gW_buf[((ci * 3 + kd) * 3 + kh) * 24 + kw * 8 + co] = pk2(w, w);
    }
}

__global__ void __launch_bounds__(256, 2)
conv3d_fused_kernel(const float* __restrict__ x,
                    const float* __restrict__ bias,
                    float* __restrict__ out)
{
    __shared__ __align__(16) float sC[18 * ROWP];   // sC[r][w] = x[r][w]
    __shared__ __align__(16) float sS[18 * ROWP];   // sS[r][k] = x[r][k-1]

    const int tid  = threadIdx.x;
    const int lane = tid & 31;
    const int bx   = blockIdx.x;
    const int ht   = bx & 7;
    const int dpos = (bx >> 3) & 31;
    const int b    = bx >> 8;
    const int h0   = ht << 4;

    // k=129 pad of the shifted copy (never overwritten; k=0 written each slab)
    if (tid < 18) sS[tid * ROWP + 129] = 0.0f;

    const int hh = tid >> 4;     // row in tile (0..15)
    const int wg = tid & 15;
    const int w0 = wg << 3;

    u64 acc[32];
    #pragma unroll
    for (int k = 0; k < 32; ++k) acc[k] = 0ull;

    for (int ci = 0; ci < 8; ++ci) {
        const float* xb = x + ((size_t)((b * 8 + ci) * 32) << 14);
        #pragma unroll 1
        for (int dz = 0; dz < 3; ++dz) {
            const int dd = dpos + dz - 1;
            if ((unsigned)dd >= 32u) continue;   // zero slice contributes nothing

            __syncthreads();  // previous slab fully consumed (and pad init on iter 0)

            // single-pass staging: 18 rows x 128 cols; each warp stages a full
            // row per iteration (lane == float4 column), writing sC and the
            // lane-rotated sS in the same pass.
            const float4* xs4 = reinterpret_cast<const float4*>(xb + ((size_t)dd << 14));
            #pragma unroll
            for (int j = 0; j < 3; ++j) {
                int i = tid + j * 256;           // 0 .. 767 (576 valid)
                int hz = i >> 5;
                bool rowok = hz < 18;
                int hg = h0 + hz - 1;
                float4 v = make_float4(0.f, 0.f, 0.f, 0.f);
                if (rowok && (unsigned)hg < 128u) v = xs4[(hg << 5) + lane];
                float pw = __shfl_up_sync(0xffffffffu, v.w, 1);
                if (lane == 0) pw = 0.0f;        // x[-1] zero pad
                if (rowok) {
                    float* rowC = &sC[hz * ROWP];
                    float* rowS = &sS[hz * ROWP];
                    *reinterpret_cast<float4*>(rowC + (lane << 2)) = v;
                    *reinterpret_cast<float4*>(rowS + (lane << 2)) =
                        make_float4(pw, v.x, v.y, v.z);
                    if (lane == 31) rowS[128] = v.w;   // sS[128] = x[127]
                }
            }
            __syncthreads();

            #pragma unroll
            for (int kh = 0; kh < 3; ++kh) {
                const int roff = (hh + kh) * ROWP;
                const ulonglong2* cp = reinterpret_cast<const ulonglong2*>(&sC[roff + w0]);
                ulonglong2 ca = cp[0];    // center pairs 0,1
                ulonglong2 cb = cp[1];    // center pairs 2,3
                const ulonglong2* sp = reinterpret_cast<const ulonglong2*>(&sS[roff + w0]);
                ulonglong2 sa = sp[0];    // left pairs 0,1
                ulonglong2 sb = sp[1];    // left pairs 2,3
                u64 sr3 = *reinterpret_cast<const u64*>(&sS[roff + w0 + 8]); // right pair 3

                const u64* wp = &cW[((ci * 3 + dz) * 3 + kh) * 24];
                #pragma unroll
                for (int cp2 = 0; cp2 < 4; ++cp2) {   // co pairs (2 couts each)
                    ulonglong2 wL = *reinterpret_cast<const ulonglong2*>(wp + 2 * cp2);
                    ulonglong2 wC = *reinterpret_cast<const ulonglong2*>(wp + 8 + 2 * cp2);
                    ulonglong2 wR = *reinterpret_cast<const ulonglong2*>(wp + 16 + 2 * cp2);
                    u64* a0 = &acc[(2 * cp2) * 4];
                    u64* a1 = &acc[(2 * cp2 + 1) * 4];
                    fma2(a0[0], sa.x, wL.x);  fma2(a0[1], sa.y, wL.x);
                    fma2(a0[2], sb.x, wL.x);  fma2(a0[3], sb.y, wL.x);
                    fma2(a0[0], ca.x, wC.x);  fma2(a0[1], ca.y, wC.x);
                    fma2(a0[2], cb.x, wC.x);  fma2(a0[3], cb.y, wC.x);
                    fma2(a0[0], sa.y, wR.x);  fma2(a0[1], sb.x, wR.x);
                    fma2(a0[2], sb.y, wR.x);  fma2(a0[3], sr3, wR.x);
                    fma2(a1[0], sa.x, wL.y);  fma2(a1[1], sa.y, wL.y);
                    fma2(a1[2], sb.x, wL.y);  fma2(a1[3], sb.y, wL.y);
                    fma2(a1[0], ca.x, wC.y);  fma2(a1[1], ca.y, wC.y);
                    fma2(a1[2], cb.x, wC.y);  fma2(a1[3], cb.y, wC.y);
                    fma2(a1[0], sa.y, wR.y);  fma2(a1[1], sb.x, wR.y);
                    fma2(a1[2], sb.y, wR.y);  fma2(a1[3], sr3, wR.y);
                }
            }
        }
    }

    // --- epilogue: activation chain + bias, vectorized coalesced stores ---
    const int hout = h0 + hh;
    #pragma unroll
    for (int co = 0; co < 8; ++co) {
        float bb = bias[co];
        float o[8];
        #pragma unroll
        for (int j = 0; j < 4; ++j) {
            float2 p = up2(acc[co * 4 + j]);
            o[2 * j]     = p.x;
            o[2 * j + 1] = p.y;
        }
        #pragma unroll
        for (int k = 0; k < 8; ++k)
            o[k] = act_chain(o[k]) + bb;

        float4* dst = reinterpret_cast<float4*>(
            out + ((size_t)((b * 8 + co) * 32 + dpos) << 14) + (hout << 7) + w0);
        dst[0] = make_float4(o[0], o[1], o[2], o[3]);
        dst[1] = make_float4(o[4], o[5], o[6], o[7]);
    }
}

extern "C" void kernel_launch(void* const* d_in, const int* in_sizes, int n_in,
                              void* d_out, int out_size)
{
    const float* x    = (const float*)d_in[0];   // (8,8,32,128,128)
    const float* wgt  = (const float*)d_in[1];   // (8,8,3,3,3)
    const float* bias = (const float*)d_in[2];   // (8,1,1,1)
    float* out = (float*)d_out;                  // (8,8,32,128,128)

    weight_splat_kernel<<<1, 256>>>(wgt);
    void* gw_ptr = nullptr;
    cudaGetSymbolAddress(&gw_ptr, gW_buf);
    cudaMemcpyToSymbolAsync(cW, gw_ptr, 1728 * sizeof(u64), 0,
                            cudaMemcpyDeviceToDevice, 0);
    conv3d_fused_kernel<<<2048, 256>>>(x, bias, out);
}